// round 5
// baseline (speedup 1.0000x reference)
#include <cuda_runtime.h>
#include <cstdint>

#define NTH 1024
#define KTOP 500
#define CAND_MAX 4096
#define NBIN 4096
#define NTASK 336

struct Smem {
    union {
        struct { unsigned int hist[NBIN]; unsigned int scan[NTH]; } h;  // fallback only
        unsigned long long cand[CAND_MAX];                              // 32 KB
    } u;
    float4 bx4[512];                          // 8 KB
    unsigned long long sup[KTOP][8];          // 32 KB
    unsigned long long keepw[8];
    int T, cntAbove, cnt;
};

__device__ __forceinline__ unsigned int mapf(float v) {
    unsigned int u = __float_as_uint(v);
    return (u & 0x80000000u) ? ~u : (u | 0x80000000u);
}
__device__ __forceinline__ float unmapf(unsigned int u) {
    return __uint_as_float((u & 0x80000000u) ? (u ^ 0x80000000u) : ~u);
}

__device__ void find_thr(Smem& S, int need, int tid, int& T_out, int& above_out) {
    int t4 = tid * 4;
    unsigned h0 = S.u.h.hist[t4], h1 = S.u.h.hist[t4 + 1];
    unsigned h2 = S.u.h.hist[t4 + 2], h3 = S.u.h.hist[t4 + 3];
    S.u.h.scan[tid] = h0 + h1 + h2 + h3;
    __syncthreads();
    for (int off = 1; off < NTH; off <<= 1) {
        unsigned add = (tid + off < NTH) ? S.u.h.scan[tid + off] : 0u;
        __syncthreads();
        S.u.h.scan[tid] += add;
        __syncthreads();
    }
    unsigned sfx = S.u.h.scan[tid];
    unsigned nxt = (tid < NTH - 1) ? S.u.h.scan[tid + 1] : 0u;
    if (sfx >= (unsigned)need && nxt < (unsigned)need) {
        unsigned c = nxt;
        unsigned hh[4] = { h0, h1, h2, h3 };
        for (int b = 3; b >= 0; b--) {
            if (c + hh[b] >= (unsigned)need) { S.T = t4 + b; S.cntAbove = (int)c; break; }
            c += hh[b];
        }
    }
    __syncthreads();
    T_out = S.T;
    above_out = S.cntAbove;
}

__global__ __launch_bounds__(NTH, 2) void retina_kernel(
    const float* __restrict__ cls3, const float* __restrict__ cls4, const float* __restrict__ cls5,
    const float* __restrict__ reg3, const float* __restrict__ reg4, const float* __restrict__ reg5,
    float* __restrict__ out)
{
    extern __shared__ unsigned char smem_raw[];
    Smem& S = *reinterpret_cast<Smem*>(smem_raw);
    const int tid = threadIdx.x;
    const int lane = tid & 31;

    // identity order: heavy lev0 first, cheap lev2 in the tail wave
    int task = blockIdx.x;
    int lev = (task < 112) ? 0 : ((task < 224) ? 1 : 2);
    int tt  = task - lev * 112;
    int img = tt / 7;
    int cls = tt % 7;

    const int H = 192 >> lev;
    const int W = H;
    const int HW = H * W;
    const float stride = (float)(8 << lev);
    const float asize  = (float)(16 << lev);

    const float* clsP = (lev == 0) ? cls3 : ((lev == 1) ? cls4 : cls5);
    const float* regP = (lev == 0) ? reg3 : ((lev == 1) ? reg4 : reg5);

    const float* plane0 = clsP + (size_t)(img * 24 + 0 * 8 + cls + 1) * HW;
    const float* plane1 = clsP + (size_t)(img * 24 + 1 * 8 + cls + 1) * HW;
    const float* plane2 = clsP + (size_t)(img * 24 + 2 * 8 + cls + 1) * HW;
    const float* planes[3] = { plane0, plane1, plane2 };

    if (tid == 0) S.cnt = 0;
    if (tid < 8) S.keepw[tid] = 0ull;
    __syncthreads();

    // ---------- fast path: single-pass threshold compaction (per-plane loops) ----------
    // compare raw floats; mapf only on accepted elements
    float thf = (lev == 0) ? -1.55f : ((lev == 1) ? -2.10f : -2.80f);

    for (int a = 0; a < 3; a++) {
        const float4* p4 = (const float4*)planes[a];
        int nv4 = HW >> 2;
        for (int i4 = tid; i4 < nv4; i4 += NTH) {
            float4 v = p4[i4];
            #pragma unroll
            for (int e = 0; e < 4; e++) {
                float f = (e == 0) ? v.x : (e == 1) ? v.y : (e == 2) ? v.z : v.w;
                if (f > thf) {
                    int pos = atomicAdd(&S.cnt, 1);
                    if (pos < CAND_MAX) {
                        unsigned n = (unsigned)((i4 * 4 + e) * 3 + a);
                        S.u.cand[pos] = ((unsigned long long)mapf(f) << 32)
                                      | (unsigned long long)(~n);
                    }
                }
            }
        }
    }
    __syncthreads();
    int cnt = S.cnt;

    // ---------- exact fallback: 12-bit histogram select (rare) ----------
    if (cnt < KTOP || cnt > CAND_MAX) {
        for (int i = tid; i < NBIN; i += NTH) S.u.h.hist[i] = 0;
        __syncthreads();
        for (int a = 0; a < 3; a++) {
            const float* p = planes[a];
            for (int i = tid; i < HW; i += NTH) {
                unsigned u = mapf(p[i]);
                int bin = (int)(u >> 20);
                unsigned m = __match_any_sync(__activemask(), bin);
                int leader = __ffs(m) - 1;
                if (lane == leader) atomicAdd(&S.u.h.hist[bin], (unsigned)__popc(m));
            }
        }
        __syncthreads();
        int T, above;
        find_thr(S, KTOP, tid, T, above);
        if (tid == 0) S.cnt = 0;
        __syncthreads();
        for (int a = 0; a < 3; a++) {
            const float* p = planes[a];
            for (int i = tid; i < HW; i += NTH) {
                unsigned u = mapf(p[i]);
                if ((int)(u >> 20) >= T) {
                    int pos = atomicAdd(&S.cnt, 1);
                    if (pos < CAND_MAX) {
                        unsigned n = (unsigned)(i * 3 + a);
                        S.u.cand[pos] = ((unsigned long long)u << 32) | (unsigned long long)(~n);
                    }
                }
            }
        }
        __syncthreads();
        cnt = S.cnt;

        if (cnt > CAND_MAX) {
            for (int i = tid; i < NBIN; i += NTH) S.u.h.hist[i] = 0;
            __syncthreads();
            for (int a = 0; a < 3; a++) {
                const float* p = planes[a];
                for (int i = tid; i < HW; i += NTH) {
                    unsigned u = mapf(p[i]);
                    if ((int)(u >> 20) == T)
                        atomicAdd(&S.u.h.hist[(u >> 8) & 0xFFFu], 1u);
                }
            }
            __syncthreads();
            int T2, ab2;
            find_thr(S, KTOP - above, tid, T2, ab2);
            if (tid == 0) S.cnt = 0;
            __syncthreads();
            for (int a = 0; a < 3; a++) {
                const float* p = planes[a];
                for (int i = tid; i < HW; i += NTH) {
                    unsigned u = mapf(p[i]);
                    int bin = (int)(u >> 20);
                    if (bin > T || (bin == T && (int)((u >> 8) & 0xFFFu) >= T2)) {
                        int pos = atomicAdd(&S.cnt, 1);
                        if (pos < CAND_MAX) {
                            unsigned n = (unsigned)(i * 3 + a);
                            S.u.cand[pos] = ((unsigned long long)u << 32) | (unsigned long long)(~n);
                        }
                    }
                }
            }
            __syncthreads();
            cnt = S.cnt;
        }
    }
    if (cnt > CAND_MAX) cnt = CAND_MAX;

    // ---------- smem bitonic sort (descending), pad to M ----------
    {
        int M = 512;
        while (M < cnt) M <<= 1;
        for (int i = cnt + tid; i < M; i += NTH) S.u.cand[i] = 0ull;
        __syncthreads();
        for (int k = 2; k <= M; k <<= 1) {
            for (int j = k >> 1; j > 0; j >>= 1) {
                if (j >= 16) __syncthreads(); else __syncwarp();
                for (int i = tid; i < M; i += NTH) {
                    int ixj = i ^ j;
                    if (ixj > i) {
                        unsigned long long a = S.u.cand[i], b = S.u.cand[ixj];
                        bool sw = ((i & k) == 0) ? (a < b) : (a > b);
                        if (sw) { S.u.cand[i] = b; S.u.cand[ixj] = a; }
                    }
                }
            }
        }
        __syncthreads();
    }

    // ---------- decode top-500, write boxes/scores/labels ----------
    long long tbase = (long long)((lev * 16 + img) * 7 + cls) * KTOP;
    float4* obox4 = (float4*)(out + tbase * 4);
    float* osc   = out + 672000 + tbase;
    float* okeep = out + 840000 + tbase;
    float* olab  = out + 1008000 + tbase;

    if (tid < 512) {
        int r = tid;
        bool valid_bit = false;
        if (r < KTOP) {
            unsigned long long key = S.u.cand[r];
            unsigned u = (unsigned)(key >> 32);
            unsigned n = ~((unsigned)key);
            float logit = unmapf(u);
            float score = __fdividef(1.0f, 1.0f + __expf(-logit));

            int a = (int)(n % 3u);
            int p = (int)(n / 3u);
            int x = p % W;
            int y = p / W;
            float sqv = (a == 0) ? 0.70710678118654752f : ((a == 1) ? 1.0f : 1.41421356237309505f);
            float wa = asize * sqv;
            float ha = asize / sqv;
            float cxa = ((float)x + 0.5f) * stride;
            float cya = ((float)y + 0.5f) * stride;

            size_t rb = (size_t)(img * 12 + a * 4) * HW + (size_t)p;
            float dx = regP[rb];
            float dy = regP[rb + HW];
            float dw = regP[rb + 2 * (size_t)HW];
            float dh = regP[rb + 3 * (size_t)HW];

            float cx = dx * wa + cxa;
            float cy = dy * ha + cya;
            float bw = __expf(dw) * wa;
            float bh = __expf(dh) * ha;
            float bx1 = cx - 0.5f * bw, by1 = cy - 0.5f * bh;
            float bx2 = cx + 0.5f * bw, by2 = cy + 0.5f * bh;

            S.bx4[r] = make_float4(bx1, by1, bx2, by2);
            obox4[r] = make_float4(bx1, by1, bx2, by2);
            osc[r] = score;
            olab[r] = (float)cls;
            valid_bit = (score > 0.05f);
        } else {
            S.bx4[r] = make_float4(1e30f, 1e30f, 1e30f, 1e30f);
        }
        unsigned b = __ballot_sync(0xFFFFFFFFu, valid_bit);
        if (lane == 0 && b)
            atomicOr(&S.keepw[r >> 6], (unsigned long long)b << ((r >> 5 & 1) * 32));
    }
    __syncthreads();

    // ---------- suppression bitmask matrix: warp-tiled 32x64, j-broadcast ----------
    {
        int warpId = tid >> 5;
        for (int t = warpId; t < 128; t += 32) {
            int tr = t >> 3, w = t & 7;
            int r0 = tr << 5;
            if (w * 64 + 63 <= r0) continue;      // tile entirely j<=i: never used
            int i = r0 + lane;
            float4 bi = S.bx4[i];
            float ai = (bi.z - bi.x) * (bi.w - bi.y);
            unsigned long long bits = 0ull;
            int jb = w << 6;
            #pragma unroll 4
            for (int b = 0; b < 64; b++) {
                float4 bj = S.bx4[jb + b];        // broadcast load
                float xx1 = fmaxf(bi.x, bj.x);
                float yy1 = fmaxf(bi.y, bj.y);
                float xx2 = fminf(bi.z, bj.z);
                float yy2 = fminf(bi.w, bj.w);
                float inter = fmaxf(xx2 - xx1, 0.0f) * fmaxf(yy2 - yy1, 0.0f);
                float aj = (bj.z - bj.x) * (bj.w - bj.y);
                float uni = fmaxf(ai + aj - inter, 1e-9f);
                if (inter > 0.5f * uni) bits |= (1ull << b);
            }
            if (i < KTOP) S.sup[i][w] = bits;
        }
    }
    __syncthreads();

    // ---------- greedy NMS: warp 0, chunk-prefetched serial + parallel cross-word ----------
    if (tid < 32) {
        for (int w = 0; w < 8; w++) {
            if (lane == 0) {
                unsigned long long snap = S.keepw[w];
                unsigned long long supm = 0ull, kept = 0ull, rem = snap;
                int base = w << 6;
                while (rem) {
                    int b0, b1 = -1, b2 = -1, b3 = -1;
                    unsigned long long s0, s1 = 0, s2 = 0, s3 = 0;
                    b0 = __ffsll((long long)rem) - 1; rem &= rem - 1;
                    s0 = S.sup[base + b0][w];
                    if (rem) { b1 = __ffsll((long long)rem) - 1; rem &= rem - 1; s1 = S.sup[base + b1][w]; }
                    if (rem) { b2 = __ffsll((long long)rem) - 1; rem &= rem - 1; s2 = S.sup[base + b2][w]; }
                    if (rem) { b3 = __ffsll((long long)rem) - 1; rem &= rem - 1; s3 = S.sup[base + b3][w]; }
                    if (!((supm >> b0) & 1ull)) { kept |= 1ull << b0; supm |= s0; }
                    if (b1 >= 0 && !((supm >> b1) & 1ull)) { kept |= 1ull << b1; supm |= s1; }
                    if (b2 >= 0 && !((supm >> b2) & 1ull)) { kept |= 1ull << b2; supm |= s2; }
                    if (b3 >= 0 && !((supm >> b3) & 1ull)) { kept |= 1ull << b3; supm |= s3; }
                }
                S.keepw[w] = kept;
            }
            __syncwarp();
            int w2 = w + 1 + lane;
            if (lane < 7 && w2 < 8) {
                unsigned long long kept = S.keepw[w];
                unsigned long long acc = 0ull;
                int base = w << 6;
                while (kept) {
                    int b = __ffsll((long long)kept) - 1; kept &= kept - 1;
                    acc |= S.sup[base + b][w2];
                }
                S.keepw[w2] &= ~acc;
            }
            __syncwarp();
        }
    }
    __syncthreads();

    for (int r = tid; r < KTOP; r += NTH)
        okeep[r] = ((S.keepw[r >> 6] >> (r & 63)) & 1ull) ? 1.0f : 0.0f;
}

extern "C" void kernel_launch(void* const* d_in, const int* in_sizes, int n_in,
                              void* d_out, int out_size) {
    const float *cls3 = nullptr, *cls4 = nullptr, *cls5 = nullptr;
    const float *reg3 = nullptr, *reg4 = nullptr, *reg5 = nullptr;
    for (int i = 0; i < n_in; i++) {
        switch (in_sizes[i]) {
            case 14155776: cls3 = (const float*)d_in[i]; break;
            case 7077888:  reg3 = (const float*)d_in[i]; break;
            case 3538944:  cls4 = (const float*)d_in[i]; break;
            case 1769472:  reg4 = (const float*)d_in[i]; break;
            case 884736:   cls5 = (const float*)d_in[i]; break;
            case 442368:   reg5 = (const float*)d_in[i]; break;
        }
    }
    cudaFuncSetAttribute(retina_kernel, cudaFuncAttributeMaxDynamicSharedMemorySize,
                         (int)sizeof(Smem));
    retina_kernel<<<NTASK, NTH, sizeof(Smem)>>>(cls3, cls4, cls5, reg3, reg4, reg5,
                                                (float*)d_out);
}

// round 6
// speedup vs baseline: 1.0908x; 1.0908x over previous
#include <cuda_runtime.h>
#include <cstdint>

#define KTOP 500
#define CAND_MAX 4096
#define NBIN 4096
#define NTASK 336

// ---------------- global scratch (static device allocations) ----------------
__device__ unsigned long long g_cand[NTASK][CAND_MAX];   // ~11 MB
__device__ int g_cnt[NTASK];
__device__ float4 g_boxes[NTASK][512];                   // ~2.8 MB
__device__ unsigned long long g_sup[NTASK][KTOP][8];     // ~10.8 MB
__device__ unsigned long long g_keep[NTASK][8];

// order-preserving map float -> uint (ascending)
__device__ __forceinline__ unsigned int mapf(float v) {
    unsigned int u = __float_as_uint(v);
    return (u & 0x80000000u) ? ~u : (u | 0x80000000u);
}
__device__ __forceinline__ float unmapf(unsigned int u) {
    return __uint_as_float((u & 0x80000000u) ? (u ^ 0x80000000u) : ~u);
}

__device__ __forceinline__ void task_info(int task, int& lev, int& img, int& cls,
                                          int& H, int& HW) {
    lev = (task < 112) ? 0 : ((task < 224) ? 1 : 2);
    int tt = task - lev * 112;
    img = tt / 7;
    cls = tt % 7;
    H = 192 >> lev;
    HW = H * H;
}

// ---------------- kernel 0: init counters ----------------
__global__ void k_init() {
    if (threadIdx.x < NTASK) g_cnt[threadIdx.x] = 0;
}

// ---------------- kernel 1: streaming threshold compaction ----------------
__global__ __launch_bounds__(512) void k_scan(
    const float* __restrict__ cls3, const float* __restrict__ cls4,
    const float* __restrict__ cls5)
{
    int task = blockIdx.x >> 2;
    int chunk = blockIdx.x & 3;
    int lev, img, cls, H, HW;
    task_info(task, lev, img, cls, H, HW);

    const float* clsP = (lev == 0) ? cls3 : ((lev == 1) ? cls4 : cls5);
    float thf = (lev == 0) ? -1.55f : ((lev == 1) ? -2.10f : -2.80f);

    int nv4 = HW >> 2;
    int start = chunk * 512 + threadIdx.x;

    #pragma unroll
    for (int a = 0; a < 3; a++) {
        const float4* p4 = (const float4*)(clsP + (size_t)(img * 24 + a * 8 + cls + 1) * HW);
        for (int i4 = start; i4 < nv4; i4 += 2048) {
            float4 v = p4[i4];
            #pragma unroll
            for (int e = 0; e < 4; e++) {
                float f = (e == 0) ? v.x : (e == 1) ? v.y : (e == 2) ? v.z : v.w;
                if (f > thf) {
                    int pos = atomicAdd(&g_cnt[task], 1);
                    if (pos < CAND_MAX) {
                        unsigned n = (unsigned)((i4 * 4 + e) * 3 + a);
                        g_cand[task][pos] = ((unsigned long long)mapf(f) << 32)
                                          | (unsigned long long)(~n);
                    }
                }
            }
        }
    }
}

// ---------------- kernel 2: sort + decode + outputs ----------------
struct SmemMain {
    union {
        struct { unsigned int hist[NBIN]; unsigned int scan[1024]; } h;
        unsigned long long cand[CAND_MAX];
    } u;
    unsigned long long keepw[8];
    int T, cntAbove, cnt;
};

__device__ void find_thr(SmemMain& S, int need, int tid, int& T_out, int& above_out) {
    int t4 = tid * 4;
    unsigned h0 = S.u.h.hist[t4], h1 = S.u.h.hist[t4 + 1];
    unsigned h2 = S.u.h.hist[t4 + 2], h3 = S.u.h.hist[t4 + 3];
    S.u.h.scan[tid] = h0 + h1 + h2 + h3;
    __syncthreads();
    for (int off = 1; off < 1024; off <<= 1) {
        unsigned add = (tid + off < 1024) ? S.u.h.scan[tid + off] : 0u;
        __syncthreads();
        S.u.h.scan[tid] += add;
        __syncthreads();
    }
    unsigned sfx = S.u.h.scan[tid];
    unsigned nxt = (tid < 1023) ? S.u.h.scan[tid + 1] : 0u;
    if (sfx >= (unsigned)need && nxt < (unsigned)need) {
        unsigned c = nxt;
        unsigned hh[4] = { h0, h1, h2, h3 };
        for (int b = 3; b >= 0; b--) {
            if (c + hh[b] >= (unsigned)need) { S.T = t4 + b; S.cntAbove = (int)c; break; }
            c += hh[b];
        }
    }
    __syncthreads();
    T_out = S.T;
    above_out = S.cntAbove;
}

__global__ __launch_bounds__(1024, 2) void k_main(
    const float* __restrict__ cls3, const float* __restrict__ cls4, const float* __restrict__ cls5,
    const float* __restrict__ reg3, const float* __restrict__ reg4, const float* __restrict__ reg5,
    float* __restrict__ out)
{
    __shared__ SmemMain S;
    const int tid = threadIdx.x;
    const int lane = tid & 31;

    int task = blockIdx.x;
    int lev, img, cls, H, HW;
    task_info(task, lev, img, cls, H, HW);
    const int W = H;
    const float stride = (float)(8 << lev);
    const float asize  = (float)(16 << lev);

    const float* clsP = (lev == 0) ? cls3 : ((lev == 1) ? cls4 : cls5);
    const float* regP = (lev == 0) ? reg3 : ((lev == 1) ? reg4 : reg5);
    const float* plane0 = clsP + (size_t)(img * 24 + 0 * 8 + cls + 1) * HW;
    const float* plane1 = clsP + (size_t)(img * 24 + 1 * 8 + cls + 1) * HW;
    const float* plane2 = clsP + (size_t)(img * 24 + 2 * 8 + cls + 1) * HW;
    const float* planes[3] = { plane0, plane1, plane2 };

    if (tid < 8) S.keepw[tid] = 0ull;
    __syncthreads();

    int cnt = g_cnt[task];

    if (cnt >= KTOP && cnt <= CAND_MAX) {
        // fast path: pull candidates from global scratch
        for (int i = tid; i < cnt; i += 1024) S.u.cand[i] = g_cand[task][i];
        __syncthreads();
    } else {
        // exact fallback: 12-bit histogram select over raw planes
        for (int i = tid; i < NBIN; i += 1024) S.u.h.hist[i] = 0;
        __syncthreads();
        for (int a = 0; a < 3; a++) {
            const float* p = planes[a];
            for (int i = tid; i < HW; i += 1024) {
                unsigned u = mapf(p[i]);
                int bin = (int)(u >> 20);
                unsigned m = __match_any_sync(__activemask(), bin);
                int leader = __ffs(m) - 1;
                if (lane == leader) atomicAdd(&S.u.h.hist[bin], (unsigned)__popc(m));
            }
        }
        __syncthreads();
        int T, above;
        find_thr(S, KTOP, tid, T, above);
        if (tid == 0) S.cnt = 0;
        __syncthreads();
        for (int a = 0; a < 3; a++) {
            const float* p = planes[a];
            for (int i = tid; i < HW; i += 1024) {
                unsigned u = mapf(p[i]);
                if ((int)(u >> 20) >= T) {
                    int pos = atomicAdd(&S.cnt, 1);
                    if (pos < CAND_MAX) {
                        unsigned n = (unsigned)(i * 3 + a);
                        S.u.cand[pos] = ((unsigned long long)u << 32) | (unsigned long long)(~n);
                    }
                }
            }
        }
        __syncthreads();
        cnt = S.cnt;

        if (cnt > CAND_MAX) {
            // refine within boundary bin on bits [19:8]
            for (int i = tid; i < NBIN; i += 1024) S.u.h.hist[i] = 0;
            __syncthreads();
            for (int a = 0; a < 3; a++) {
                const float* p = planes[a];
                for (int i = tid; i < HW; i += 1024) {
                    unsigned u = mapf(p[i]);
                    if ((int)(u >> 20) == T)
                        atomicAdd(&S.u.h.hist[(u >> 8) & 0xFFFu], 1u);
                }
            }
            __syncthreads();
            int T2, ab2;
            find_thr(S, KTOP - above, tid, T2, ab2);
            if (tid == 0) S.cnt = 0;
            __syncthreads();
            for (int a = 0; a < 3; a++) {
                const float* p = planes[a];
                for (int i = tid; i < HW; i += 1024) {
                    unsigned u = mapf(p[i]);
                    int bin = (int)(u >> 20);
                    if (bin > T || (bin == T && (int)((u >> 8) & 0xFFFu) >= T2)) {
                        int pos = atomicAdd(&S.cnt, 1);
                        if (pos < CAND_MAX) {
                            unsigned n = (unsigned)(i * 3 + a);
                            S.u.cand[pos] = ((unsigned long long)u << 32) | (unsigned long long)(~n);
                        }
                    }
                }
            }
            __syncthreads();
            cnt = S.cnt;
        }
        if (cnt > CAND_MAX) cnt = CAND_MAX;
    }

    // ---------- smem bitonic sort (descending), pad to M ----------
    {
        int M = 512;
        while (M < cnt) M <<= 1;
        for (int i = cnt + tid; i < M; i += 1024) S.u.cand[i] = 0ull;
        __syncthreads();
        for (int k = 2; k <= M; k <<= 1) {
            for (int j = k >> 1; j > 0; j >>= 1) {
                for (int i = tid; i < M; i += 1024) {
                    int ixj = i ^ j;
                    if (ixj > i) {
                        unsigned long long a = S.u.cand[i], b = S.u.cand[ixj];
                        bool sw = ((i & k) == 0) ? (a < b) : (a > b);
                        if (sw) { S.u.cand[i] = b; S.u.cand[ixj] = a; }
                    }
                }
                __syncthreads();
            }
        }
    }

    // ---------- decode top-500, write boxes/scores/labels + global scratch ----------
    long long tbase = (long long)((lev * 16 + img) * 7 + cls) * KTOP;
    float4* obox4 = (float4*)(out + tbase * 4);
    float* osc   = out + 672000 + tbase;
    float* olab  = out + 1008000 + tbase;

    if (tid < 512) {
        int r = tid;
        bool valid_bit = false;
        if (r < KTOP) {
            unsigned long long key = S.u.cand[r];
            unsigned u = (unsigned)(key >> 32);
            unsigned n = ~((unsigned)key);
            float logit = unmapf(u);
            float score = __fdividef(1.0f, 1.0f + __expf(-logit));

            int a = (int)(n % 3u);
            int p = (int)(n / 3u);
            int x = p % W;
            int y = p / W;
            float sqv = (a == 0) ? 0.70710678118654752f : ((a == 1) ? 1.0f : 1.41421356237309505f);
            float wa = asize * sqv;
            float ha = asize / sqv;
            float cxa = ((float)x + 0.5f) * stride;
            float cya = ((float)y + 0.5f) * stride;

            size_t rb = (size_t)(img * 12 + a * 4) * HW + (size_t)p;
            float dx = regP[rb];
            float dy = regP[rb + HW];
            float dw = regP[rb + 2 * (size_t)HW];
            float dh = regP[rb + 3 * (size_t)HW];

            float cx = dx * wa + cxa;
            float cy = dy * ha + cya;
            float bw = __expf(dw) * wa;
            float bh = __expf(dh) * ha;
            float bx1 = cx - 0.5f * bw, by1 = cy - 0.5f * bh;
            float bx2 = cx + 0.5f * bw, by2 = cy + 0.5f * bh;

            float4 bxv = make_float4(bx1, by1, bx2, by2);
            g_boxes[task][r] = bxv;
            obox4[r] = bxv;
            osc[r] = score;
            olab[r] = (float)cls;
            valid_bit = (score > 0.05f);
        } else {
            g_boxes[task][r] = make_float4(1e30f, 1e30f, 1e30f, 1e30f);
        }
        unsigned b = __ballot_sync(0xFFFFFFFFu, valid_bit);
        if (lane == 0 && b)
            atomicOr(&S.keepw[r >> 6], (unsigned long long)b << ((r >> 5 & 1) * 32));
    }
    __syncthreads();
    if (tid < 8) g_keep[task][tid] = S.keepw[tid];
}

// ---------------- kernel 3: IoU suppression tiles (1 warp = 1 tile 32x64) ----------------
__global__ __launch_bounds__(256) void k_iou() {
    __shared__ float4 sb[512];
    __shared__ float sa[512];
    int task = blockIdx.x / 9;
    int sub  = blockIdx.x % 9;
    int tid = threadIdx.x;

    for (int i = tid; i < 512; i += 256) {
        float4 b = g_boxes[task][i];
        sb[i] = b;
        sa[i] = (b.z - b.x) * (b.w - b.y);
    }
    __syncthreads();

    int t = sub * 8 + (tid >> 5);
    if (t < 72) {
        // map t -> (tr, w): tiles with w >= tr>>1 (only j>i halves needed downstream)
        int tr = 0, base = 0;
        while (true) {
            int c = 8 - (tr >> 1);
            if (t < base + c) break;
            base += c;
            tr++;
        }
        int w = (tr >> 1) + (t - base);

        int lane = tid & 31;
        int i = tr * 32 + lane;
        float4 bi = sb[i];
        float ai = sa[i];
        unsigned long long bits = 0ull;
        int jb = w << 6;
        #pragma unroll 4
        for (int b = 0; b < 64; b++) {
            float4 bj = sb[jb + b];           // broadcast
            float xx1 = fmaxf(bi.x, bj.x);
            float yy1 = fmaxf(bi.y, bj.y);
            float xx2 = fminf(bi.z, bj.z);
            float yy2 = fminf(bi.w, bj.w);
            float inter = fmaxf(xx2 - xx1, 0.0f) * fmaxf(yy2 - yy1, 0.0f);
            // iou > 0.5  <=>  3*inter > ai+aj   (union = ai+aj-inter > 0)
            if (3.0f * inter > ai + sa[jb + b]) bits |= (1ull << b);
        }
        if (i < KTOP) g_sup[task][i][w] = bits;
    }
}

// ---------------- kernel 4: greedy NMS + keep output ----------------
__global__ __launch_bounds__(256) void k_nms(float* __restrict__ out) {
    __shared__ unsigned long long s_sup[KTOP * 8];
    __shared__ unsigned long long keepw[8];
    int task = blockIdx.x;
    int tid = threadIdx.x;
    int lane = tid & 31;

    const unsigned long long* gs = &g_sup[task][0][0];
    for (int i = tid; i < KTOP * 8; i += 256) s_sup[i] = gs[i];
    if (tid < 8) keepw[tid] = g_keep[task][tid];
    __syncthreads();

    if (tid < 32) {
        for (int w = 0; w < 8; w++) {
            if (lane == 0) {
                unsigned long long snap = keepw[w];
                unsigned long long supm = 0ull, kept = 0ull, rem = snap;
                int base = w << 6;
                while (rem) {
                    int b0, b1 = -1, b2 = -1, b3 = -1;
                    unsigned long long s0, s1 = 0, s2 = 0, s3 = 0;
                    b0 = __ffsll((long long)rem) - 1; rem &= rem - 1;
                    s0 = s_sup[(base + b0) * 8 + w];
                    if (rem) { b1 = __ffsll((long long)rem) - 1; rem &= rem - 1; s1 = s_sup[(base + b1) * 8 + w]; }
                    if (rem) { b2 = __ffsll((long long)rem) - 1; rem &= rem - 1; s2 = s_sup[(base + b2) * 8 + w]; }
                    if (rem) { b3 = __ffsll((long long)rem) - 1; rem &= rem - 1; s3 = s_sup[(base + b3) * 8 + w]; }
                    if (!((supm >> b0) & 1ull)) { kept |= 1ull << b0; supm |= s0; }
                    if (b1 >= 0 && !((supm >> b1) & 1ull)) { kept |= 1ull << b1; supm |= s1; }
                    if (b2 >= 0 && !((supm >> b2) & 1ull)) { kept |= 1ull << b2; supm |= s2; }
                    if (b3 >= 0 && !((supm >> b3) & 1ull)) { kept |= 1ull << b3; supm |= s3; }
                }
                keepw[w] = kept;
            }
            __syncwarp();
            int w2 = w + 1 + lane;
            if (lane < 7 && w2 < 8) {
                unsigned long long kept = keepw[w];
                unsigned long long acc = 0ull;
                int base = w << 6;
                while (kept) {
                    int b = __ffsll((long long)kept) - 1; kept &= kept - 1;
                    acc |= s_sup[(base + b) * 8 + w2];
                }
                keepw[w2] &= ~acc;
            }
            __syncwarp();
        }
    }
    __syncthreads();

    int lev = (task < 112) ? 0 : ((task < 224) ? 1 : 2);
    int tt  = task - lev * 112;
    long long tbase = (long long)((lev * 16 + tt / 7) * 7 + tt % 7) * KTOP;
    float* okeep = out + 840000 + tbase;
    for (int r = tid; r < KTOP; r += 256)
        okeep[r] = ((keepw[r >> 6] >> (r & 63)) & 1ull) ? 1.0f : 0.0f;
}

// ---------------- launcher ----------------
extern "C" void kernel_launch(void* const* d_in, const int* in_sizes, int n_in,
                              void* d_out, int out_size) {
    const float *cls3 = nullptr, *cls4 = nullptr, *cls5 = nullptr;
    const float *reg3 = nullptr, *reg4 = nullptr, *reg5 = nullptr;
    for (int i = 0; i < n_in; i++) {
        switch (in_sizes[i]) {
            case 14155776: cls3 = (const float*)d_in[i]; break;
            case 7077888:  reg3 = (const float*)d_in[i]; break;
            case 3538944:  cls4 = (const float*)d_in[i]; break;
            case 1769472:  reg4 = (const float*)d_in[i]; break;
            case 884736:   cls5 = (const float*)d_in[i]; break;
            case 442368:   reg5 = (const float*)d_in[i]; break;
        }
    }
    float* out = (float*)d_out;
    k_init<<<1, NTASK>>>();
    k_scan<<<NTASK * 4, 512>>>(cls3, cls4, cls5);
    k_main<<<NTASK, 1024>>>(cls3, cls4, cls5, reg3, reg4, reg5, out);
    k_iou<<<NTASK * 9, 256>>>();
    k_nms<<<NTASK, 256>>>(out);
}